// round 8
// baseline (speedup 1.0000x reference)
#include <cuda_runtime.h>
#include <math.h>
#include <stdint.h>

#define NN 50000
#define FF 128
#define CC 512
#define EE 800000
#define HH 256

#define OFF_ADJ   (CC*FF)
#define OFF_BATCH (OFF_ADJ + CC*CC)
#define OFF_S     (OFF_BATCH + CC)

// ---------------- scratch ----------------------------------------------------
__device__ __align__(16) float g_l[(size_t)NN * CC];
__device__ __align__(16) float g_z[(size_t)NN * HH];
__device__ __align__(16) float g_t[(size_t)NN * HH];
__device__ float g_inv[NN];
__device__ int   g_deg[NN];
__device__ int   g_off[NN + 1];
__device__ int   g_cur[NN];
__device__ int   g_csr_src[EE];
__device__ float g_csr_cf[EE];
__device__ int   g_cluster[NN];
__device__ float g_hs[NN];
__device__ int   g_sdeg[NN];
__device__ float g_invs[NN];
__device__ float g_sagg[NN];
__device__ float g_score[NN];
__device__ int   g_icnt[CC];
__device__ int   g_segkey[CC];
__device__ int   g_segidx[CC];

__device__ __forceinline__ int fkey(float f) {
    int b = __float_as_int(f);
    return b < 0 ? (b ^ 0x7FFFFFFF) : b;
}
__device__ __forceinline__ float fdec(int k) {
    return __int_as_float(k < 0 ? (k ^ 0x7FFFFFFF) : k);
}

// ---------------- cp.async helpers -------------------------------------------
__device__ __forceinline__ void cp16(void* smem, const void* gmem) {
    uint32_t s = (uint32_t)__cvta_generic_to_shared(smem);
    asm volatile("cp.async.cg.shared.global [%0], [%1], 16;" :: "r"(s), "l"(gmem));
}
#define CP_COMMIT() asm volatile("cp.async.commit_group;")
#define CP_WAIT(N)  asm volatile("cp.async.wait_group %0;" :: "n"(N))

// ---------------- init --------------------------------------------------------
__global__ void k_init(float* out) {
    int i = blockIdx.x * blockDim.x + threadIdx.x;
    int stride = gridDim.x * blockDim.x;
    for (int j = i; j < NN; j += stride) { g_deg[j] = 0; g_sdeg[j] = 0; g_sagg[j] = 0.f; }
    for (int j = i; j < CC; j += stride) {
        g_icnt[j] = 0; g_segkey[j] = (int)0x80000000; g_segidx[j] = NN;
        out[OFF_BATCH + j] = 0.f;
    }
    for (int j = i; j < CC * CC; j += stride) out[OFF_ADJ + j] = 0.f;
}

// single block: degree histogram + scan + inv + cur (frees capture slot 3)
__global__ void __launch_bounds__(1024) k_scanall(const int* __restrict__ ei) {
    int t = threadIdx.x;
    for (int e = t; e < EE; e += 1024) atomicAdd(&g_deg[ei[EE + e]], 1);
    __syncthreads();

    __shared__ int ssum[1024];
    const int chunk = (NN + 1023) / 1024;
    int b = t * chunk, e = min(b + chunk, NN);
    int s = 0;
    for (int i = b; i < e; i++) s += g_deg[i];
    ssum[t] = s;
    __syncthreads();
    for (int off = 1; off < 1024; off <<= 1) {
        int v = (t >= off) ? ssum[t - off] : 0;
        __syncthreads();
        ssum[t] += v;
        __syncthreads();
    }
    int run = (t > 0) ? ssum[t - 1] : 0;
    for (int i = b; i < e; i++) {
        int d = g_deg[i];
        g_off[i] = run;
        g_cur[i] = run;
        g_inv[i] = rsqrtf((float)d + 1.0f);
        run += d;
    }
    if (t == 1023) g_off[NN] = ssum[1023];
}

__global__ void k_fill(const int* __restrict__ ei) {
    int e = blockIdx.x * blockDim.x + threadIdx.x;
    if (e >= EE) return;
    int s = ei[e], d = ei[EE + e];
    int p = atomicAdd(&g_cur[d], 1);
    g_csr_src[p] = s;
    g_csr_cf[p] = g_inv[s] * g_inv[d];
}

// ---------------- aggregation: cp.async double-buffered pipeline -------------
// One node per block (D threads). Edge rows are prefetched to smem via
// cp.async (8 rows per stage, 2 stages) so gather latency is overlapped with
// accumulation instead of exposed per edge-chain.
template <int D>
__global__ void __launch_bounds__(D) k_aggp(const float* __restrict__ h,
                                            float* __restrict__ z) {
    constexpr int EPB = 8;          // edges per stage
    constexpr int TR  = D / 4;      // threads per row (16B each)
    constexpr int RPR = D / TR;     // rows per issue round = 4
    __shared__ int   s_src[128];
    __shared__ float s_cf[128];
    __shared__ float s_dat[2][EPB][D];

    int i = blockIdx.x;
    int t = threadIdx.x;
    int beg = g_off[i], end = g_off[i + 1];
    float inv = g_inv[i];
    float acc = inv * inv * __ldg(h + (size_t)i * D + t);

    const int rrow = t / TR;          // 0..3
    const int rcol = (t % TR) * 4;    // float offset within row

    for (int c0 = beg; c0 < end; c0 += 128) {
        int m = min(128, end - c0);
        __syncthreads();
        if (t < m) { s_src[t] = g_csr_src[c0 + t]; s_cf[t] = g_csr_cf[c0 + t]; }
        __syncthreads();

        int nst = (m + EPB - 1) / EPB;
        // prefetch stage 0
        {
            int R = min(EPB, m);
#pragma unroll
            for (int k = 0; k < EPB / RPR; k++) {
                int r = rrow + k * RPR;
                if (r < R)
                    cp16(&s_dat[0][r][rcol], h + (size_t)s_src[r] * D + rcol);
            }
            CP_COMMIT();
        }
        for (int st = 0; st < nst; st++) {
            int b = st & 1;
            if (st + 1 < nst) {
                int e0 = (st + 1) * EPB;
                int R = min(EPB, m - e0);
#pragma unroll
                for (int k = 0; k < EPB / RPR; k++) {
                    int r = rrow + k * RPR;
                    if (r < R)
                        cp16(&s_dat[b ^ 1][r][rcol],
                             h + (size_t)s_src[e0 + r] * D + rcol);
                }
                CP_COMMIT();
                CP_WAIT(1);
            } else {
                CP_WAIT(0);
            }
            __syncthreads();
            int e0 = st * EPB;
            int R = min(EPB, m - e0);
#pragma unroll
            for (int e = 0; e < EPB; e++)
                if (e < R) acc = fmaf(s_cf[e0 + e], s_dat[b][e][t], acc);
            __syncthreads();
        }
    }
    z[(size_t)i * D + t] = acc;
}

// ---------------- split-tf32 TC GEMM (measured 128x128 variant) --------------
__device__ __forceinline__ uint32_t f2tf(float f) {
    uint32_t r;
    asm("cvt.rna.tf32.f32 %0, %1;" : "=r"(r) : "f"(f));
    return r;
}
__device__ __forceinline__ void mma_tf32(float4& d,
                                         uint32_t a0, uint32_t a1, uint32_t a2, uint32_t a3,
                                         uint32_t b0, uint32_t b1) {
    asm volatile("mma.sync.aligned.m16n8k8.row.col.f32.tf32.tf32.f32 "
                 "{%0,%1,%2,%3}, {%4,%5,%6,%7}, {%8,%9}, {%0,%1,%2,%3};"
                 : "+f"(d.x), "+f"(d.y), "+f"(d.z), "+f"(d.w)
                 : "r"(a0), "r"(a1), "r"(a2), "r"(a3), "r"(b0), "r"(b1));
}

#define TCSTRIDE 136

__global__ void __launch_bounds__(256) k_tcgemm(const float* __restrict__ A,
                                                const float* __restrict__ B,
                                                const float* __restrict__ bias,
                                                float* __restrict__ Cm,
                                                int M, int K, int Nc, int epi) {
    __shared__ uint32_t Ah[2][8][TCSTRIDE];
    __shared__ uint32_t Al[2][8][TCSTRIDE];
    __shared__ uint32_t Bh[2][8][TCSTRIDE];
    __shared__ uint32_t Bl[2][8][TCSTRIDE];

    const int tid = threadIdx.x;
    const int wid = tid >> 5;
    const int lane = tid & 31;
    const int q = lane >> 2;
    const int t4 = lane & 3;
    const int m0 = (wid & 3) * 32;
    const int n0 = (wid >> 2) * 64;

    const int rowBase = blockIdx.y * 128;
    const int colBase = blockIdx.x * 128;

    const int ar = tid >> 1;
    const int ac4 = (tid & 1) * 4;
    const int br = tid >> 5;
    const int bc4 = (tid & 31) * 4;
    const bool aok = (rowBase + ar) < M;
    const float* Aptr = A + (size_t)(rowBase + ar) * K + ac4;
    const float* Bptr = B + (size_t)br * Nc + colBase + bc4;

    float4 acc[2][8];
#pragma unroll
    for (int mi = 0; mi < 2; mi++)
#pragma unroll
        for (int ni = 0; ni < 8; ni++) acc[mi][ni] = make_float4(0.f, 0.f, 0.f, 0.f);

#define SPLIT_STORE(arrH, arrL, BUF, D0, D1, V)                      \
    {                                                                \
        uint32_t h_ = f2tf(V);                                       \
        float lo_ = (V) - __uint_as_float(h_);                       \
        arrH[BUF][D0][D1] = h_;                                      \
        arrL[BUF][D0][D1] = f2tf(lo_);                               \
    }
#define LOAD_TILE(BUF, K0)                                                        \
    {                                                                             \
        float4 va = aok ? *(const float4*)(Aptr + (K0))                           \
                        : make_float4(0.f, 0.f, 0.f, 0.f);                        \
        float4 vb = *(const float4*)(Bptr + (size_t)(K0) * Nc);                   \
        SPLIT_STORE(Ah, Al, BUF, ac4 + 0, ar, va.x)                               \
        SPLIT_STORE(Ah, Al, BUF, ac4 + 1, ar, va.y)                               \
        SPLIT_STORE(Ah, Al, BUF, ac4 + 2, ar, va.z)                               \
        SPLIT_STORE(Ah, Al, BUF, ac4 + 3, ar, va.w)                               \
        SPLIT_STORE(Bh, Bl, BUF, br, bc4 + 0, vb.x)                               \
        SPLIT_STORE(Bh, Bl, BUF, br, bc4 + 1, vb.y)                               \
        SPLIT_STORE(Bh, Bl, BUF, br, bc4 + 2, vb.z)                               \
        SPLIT_STORE(Bh, Bl, BUF, br, bc4 + 3, vb.w)                               \
    }

#define COMPUTE_TILE(BUF)                                                          \
    {                                                                              \
        uint32_t ah[2][4], al[2][4];                                               \
        _Pragma("unroll")                                                          \
        for (int mi = 0; mi < 2; mi++) {                                           \
            int mrow = m0 + mi * 16;                                               \
            ah[mi][0] = Ah[BUF][t4][mrow + q];                                     \
            ah[mi][1] = Ah[BUF][t4][mrow + q + 8];                                 \
            ah[mi][2] = Ah[BUF][t4 + 4][mrow + q];                                 \
            ah[mi][3] = Ah[BUF][t4 + 4][mrow + q + 8];                             \
            al[mi][0] = Al[BUF][t4][mrow + q];                                     \
            al[mi][1] = Al[BUF][t4][mrow + q + 8];                                 \
            al[mi][2] = Al[BUF][t4 + 4][mrow + q];                                 \
            al[mi][3] = Al[BUF][t4 + 4][mrow + q + 8];                             \
        }                                                                          \
        _Pragma("unroll")                                                          \
        for (int ni = 0; ni < 8; ni++) {                                           \
            int ncol = n0 + ni * 8 + q;                                            \
            uint32_t bh0 = Bh[BUF][t4][ncol];                                      \
            uint32_t bh1 = Bh[BUF][t4 + 4][ncol];                                  \
            uint32_t bl0 = Bl[BUF][t4][ncol];                                      \
            uint32_t bl1 = Bl[BUF][t4 + 4][ncol];                                  \
            _Pragma("unroll")                                                      \
            for (int mi = 0; mi < 2; mi++) {                                       \
                mma_tf32(acc[mi][ni], ah[mi][0], ah[mi][1], ah[mi][2], ah[mi][3],  \
                         bh0, bh1);                                                \
                mma_tf32(acc[mi][ni], ah[mi][0], ah[mi][1], ah[mi][2], ah[mi][3],  \
                         bl0, bl1);                                                \
                mma_tf32(acc[mi][ni], al[mi][0], al[mi][1], al[mi][2], al[mi][3],  \
                         bh0, bh1);                                                \
            }                                                                      \
        }                                                                          \
    }

    LOAD_TILE(0, 0)
    __syncthreads();

    int buf = 0;
    for (int k0 = 8; k0 < K; k0 += 8) {
        COMPUTE_TILE(buf)
        LOAD_TILE(buf ^ 1, k0)
        __syncthreads();
        buf ^= 1;
    }
    COMPUTE_TILE(buf)

#pragma unroll
    for (int mi = 0; mi < 2; mi++) {
#pragma unroll
        for (int ni = 0; ni < 8; ni++) {
            int col = colBase + n0 + ni * 8 + 2 * t4;
            float bb0 = 0.f, bb1 = 0.f;
            if (epi) { bb0 = bias[col]; bb1 = bias[col + 1]; }
            int r0 = rowBase + m0 + mi * 16 + q;
            int r1 = r0 + 8;
            float4 v = acc[mi][ni];
            float o0 = v.x + bb0, o1 = v.y + bb1, o2 = v.z + bb0, o3 = v.w + bb1;
            if (epi) {
                o0 = fmaxf(o0, 0.f); o1 = fmaxf(o1, 0.f);
                o2 = fmaxf(o2, 0.f); o3 = fmaxf(o3, 0.f);
            }
            if (r0 < M) *(float2*)(Cm + (size_t)r0 * Nc + col) = make_float2(o0, o1);
            if (r1 < M) *(float2*)(Cm + (size_t)r1 * Nc + col) = make_float2(o2, o3);
        }
    }
}

// ---------------- softmax + argmax (first-max tie rule) ----------------------
__global__ void __launch_bounds__(256) k_softmax(const float* __restrict__ logits,
                                                 float* __restrict__ S) {
    int i = blockIdx.x;
    int t = threadIdx.x;
    int w = t >> 5, lane = t & 31;
    const float* row = logits + (size_t)i * CC;
    float v0 = row[t], v1 = row[t + 256];
    float bv = v0; int bi = t;
    if (v1 > bv) { bv = v1; bi = t + 256; }

#pragma unroll
    for (int off = 16; off > 0; off >>= 1) {
        float ov = __shfl_xor_sync(0xFFFFFFFF, bv, off);
        int   oi = __shfl_xor_sync(0xFFFFFFFF, bi, off);
        if (ov > bv || (ov == bv && oi < bi)) { bv = ov; bi = oi; }
    }
    __shared__ float swv[8];
    __shared__ int   swi[8];
    if (lane == 0) { swv[w] = bv; swi[w] = bi; }
    __syncthreads();
    float m = swv[0]; int am = swi[0];
#pragma unroll
    for (int k = 1; k < 8; k++) {
        float ov = swv[k]; int oi = swi[k];
        if (ov > m || (ov == m && oi < am)) { m = ov; am = oi; }
    }
    if (t == 0) g_cluster[i] = am;

    float e0 = expf(v0 - m), e1 = expf(v1 - m);
    float s = e0 + e1;
#pragma unroll
    for (int off = 16; off > 0; off >>= 1)
        s += __shfl_xor_sync(0xFFFFFFFF, s, off);
    __shared__ float sws[8];
    if (lane == 0) sws[w] = s;
    __syncthreads();
    float tot = sws[0] + sws[1] + sws[2] + sws[3] + sws[4] + sws[5] + sws[6] + sws[7];
    float invsum = 1.0f / tot;
    S[(size_t)i * CC + t]       = e0 * invsum;
    S[(size_t)i * CC + t + 256] = e1 * invsum;
}

// ---------------- score layer -------------------------------------------------
__global__ void k_hs(const float* __restrict__ x, const float* __restrict__ Ws) {
    int g = blockIdx.x * blockDim.x + threadIdx.x;
    int w = g >> 5, lane = g & 31;
    if (w >= NN) return;
    float4 xv = __ldg((const float4*)x + (size_t)w * 32 + lane);
    float4 wv = __ldg((const float4*)Ws + lane);
    float s = xv.x * wv.x + xv.y * wv.y + xv.z * wv.z + xv.w * wv.w;
#pragma unroll
    for (int off = 16; off > 0; off >>= 1) s += __shfl_down_sync(0xFFFFFFFF, s, off);
    if (lane == 0) g_hs[w] = s;
}

__global__ void k_intradeg(const int* __restrict__ ei) {
    int e = blockIdx.x * blockDim.x + threadIdx.x;
    if (e >= EE) return;
    int s = ei[e], d = ei[EE + e];
    int cs = g_cluster[s], cd = g_cluster[d];
    if (cs == cd) {
        atomicAdd(&g_sdeg[d], 1);
        atomicAdd(&g_icnt[cs], 1);
    }
}

__global__ void k_invs() {
    int i = blockIdx.x * blockDim.x + threadIdx.x;
    if (i < NN) g_invs[i] = rsqrtf((float)g_sdeg[i] + 1.0f);
}

__global__ void k_sagg(const int* __restrict__ ei) {
    int e = blockIdx.x * blockDim.x + threadIdx.x;
    if (e >= EE) return;
    int s = ei[e], d = ei[EE + e];
    if (g_cluster[s] == g_cluster[d])
        atomicAdd(&g_sagg[d], g_invs[s] * g_invs[d] * g_hs[s]);
}

__global__ void k_score(const float* __restrict__ bs) {
    int i = blockIdx.x * blockDim.x + threadIdx.x;
    if (i >= NN) return;
    float inv = g_invs[i];
    float v = g_sagg[i] + inv * inv * g_hs[i] + bs[0];
    float sc = tanhf(v);
    g_score[i] = sc;
    atomicMax(&g_segkey[g_cluster[i]], fkey(sc));
}

__global__ void k_segidx() {
    int i = blockIdx.x * blockDim.x + threadIdx.x;
    if (i >= NN) return;
    int c = g_cluster[i];
    float mx = fdec(g_segkey[c]);
    if (g_score[i] >= mx) atomicMin(&g_segidx[c], i);
}

// ---------------- pooling + adjacency ----------------------------------------
__global__ void __launch_bounds__(128) k_pool(const float* __restrict__ x,
                                              float* __restrict__ out) {
    int c = blockIdx.x;
    bool ne = g_icnt[c] > 0;
    float alpha = ne ? fdec(g_segkey[c]) : 0.f;
    int idx = min(g_segidx[c], NN - 1);
    out[(size_t)c * FF + threadIdx.x] = x[(size_t)idx * FF + threadIdx.x] * alpha;
}

__global__ void k_adj(const int* __restrict__ ei, float* __restrict__ out) {
    int e = blockIdx.x * blockDim.x + threadIdx.x;
    if (e >= EE) return;
    int cs = g_cluster[ei[e]], cd = g_cluster[ei[EE + e]];
    if (cs != cd && g_icnt[cs] > 0 && g_icnt[cd] > 0)
        out[OFF_ADJ + (size_t)cs * CC + cd] = 1.0f;
}

// ---------------- launch ------------------------------------------------------
extern "C" void kernel_launch(void* const* d_in, const int* in_sizes, int n_in,
                              void* d_out, int out_size) {
    const float* x   = (const float*)d_in[0];
    const int*   ei  = (const int*)d_in[1];
    const float* W1  = (const float*)d_in[3];
    const float* b1  = (const float*)d_in[4];
    const float* W2  = (const float*)d_in[5];
    const float* b2  = (const float*)d_in[6];
    const float* W3  = (const float*)d_in[7];
    const float* b3  = (const float*)d_in[8];
    const float* Ws  = (const float*)d_in[9];
    const float* bs  = (const float*)d_in[10];
    float* out = (float*)d_out;

    const int EB = (EE + 255) / 256;
    const int NB = (NN + 255) / 256;

    k_init<<<512, 256>>>(out);          // 0
    k_scanall<<<1, 1024>>>(ei);         // 1 (deg + scan + inv + cur)
    k_fill<<<EB, 256>>>(ei);            // 2
    // 3: layer-1 aggregation  [PROFILED]
    k_aggp<128><<<NN, 128>>>(x, g_z);
    {
        dim3 g(HH / 128, (NN + 127) / 128);
        k_tcgemm<<<g, 256>>>(g_z, W1, b1, g_t, NN, FF, HH, 1);
    }
    // layer 2
    k_aggp<256><<<NN, 256>>>(g_t, g_z);
    {
        dim3 g(HH / 128, (NN + 127) / 128);
        k_tcgemm<<<g, 256>>>(g_z, W2, b2, g_t, NN, HH, HH, 1);
    }
    // layer 3
    k_aggp<256><<<NN, 256>>>(g_t, g_z);
    {
        dim3 g(CC / 128, (NN + 127) / 128);
        k_tcgemm<<<g, 256>>>(g_z, W3, b3, g_l, NN, HH, CC, 1);
    }

    k_softmax<<<NN, 256>>>(g_l, out + OFF_S);

    k_hs<<<(NN * 32 + 255) / 256, 256>>>(x, Ws);
    k_intradeg<<<EB, 256>>>(ei);
    k_invs<<<NB, 256>>>();
    k_sagg<<<EB, 256>>>(ei);
    k_score<<<NB, 256>>>(bs);
    k_segidx<<<NB, 256>>>();
    k_pool<<<CC, 128>>>(x, out);
    k_adj<<<EB, 256>>>(ei, out);

    (void)in_sizes; (void)n_in; (void)out_size;
}

// round 9
// speedup vs baseline: 1.6261x; 1.6261x over previous
#include <cuda_runtime.h>
#include <math.h>
#include <stdint.h>

#define NN 50000
#define FF 128
#define CC 512
#define EE 800000
#define HH 256

// Output layout: new_x [C,F], new_adj [C,C], new_batch [C], S [N,C]
#define OFF_ADJ   (CC*FF)
#define OFF_BATCH (OFF_ADJ + CC*CC)
#define OFF_S     (OFF_BATCH + CC)

// ---------------- scratch (exactly R2's layout) ------------------------------
__device__ __align__(16) float g_h[(size_t)NN * CC];   // GEMM outputs (<=512 wide)
__device__ __align__(16) float g_z[(size_t)NN * HH];   // agg outputs (<=256 wide)
__device__ float g_inv[NN];
__device__ int   g_deg[NN];
__device__ int   g_off[NN + 1];
__device__ int   g_cur[NN];
__device__ int   g_csr_src[EE];
__device__ float g_csr_cf[EE];
__device__ int   g_cluster[NN];
__device__ float g_hs[NN];
__device__ int   g_sdeg[NN];
__device__ float g_invs[NN];
__device__ float g_sagg[NN];
__device__ float g_score[NN];
__device__ int   g_icnt[CC];
__device__ int   g_segkey[CC];
__device__ int   g_segidx[CC];
__device__ int   g_bsum[256];
__device__ int   g_bpref[256];

__device__ __forceinline__ int fkey(float f) {
    int b = __float_as_int(f);
    return b < 0 ? (b ^ 0x7FFFFFFF) : b;
}
__device__ __forceinline__ float fdec(int k) {
    return __int_as_float(k < 0 ? (k ^ 0x7FFFFFFF) : k);
}

// ---------------- init / degree / csr (R2 exact) -----------------------------
__global__ void k_init(float* out) {
    int i = blockIdx.x * blockDim.x + threadIdx.x;
    int stride = gridDim.x * blockDim.x;
    for (int j = i; j < NN; j += stride) { g_deg[j] = 0; g_sdeg[j] = 0; g_sagg[j] = 0.f; }
    for (int j = i; j < CC; j += stride) {
        g_icnt[j] = 0; g_segkey[j] = (int)0x80000000; g_segidx[j] = NN;
        out[OFF_BATCH + j] = 0.f;
    }
    for (int j = i; j < CC * CC; j += stride) out[OFF_ADJ + j] = 0.f;
}

__global__ void k_deg(const int* __restrict__ ei) {
    int e = blockIdx.x * blockDim.x + threadIdx.x;
    if (e < EE) atomicAdd(&g_deg[ei[EE + e]], 1);
}

__global__ void k_inv() {
    int i = blockIdx.x * blockDim.x + threadIdx.x;
    if (i < NN) g_inv[i] = rsqrtf((float)g_deg[i] + 1.0f);
}

__global__ void __launch_bounds__(256) k_scan1() {
    __shared__ int s[256];
    int t = threadIdx.x;
    int i = blockIdx.x * 256 + t;
    int v = (i < NN) ? g_deg[i] : 0;
    s[t] = v;
    __syncthreads();
    for (int off = 1; off < 256; off <<= 1) {
        int u = (t >= off) ? s[t - off] : 0;
        __syncthreads();
        s[t] += u;
        __syncthreads();
    }
    if (i < NN) g_off[i] = s[t] - v;
    if (t == 255) g_bsum[blockIdx.x] = s[255];
}
__global__ void __launch_bounds__(256) k_scan2(int nblocks) {
    __shared__ int s[256];
    int t = threadIdx.x;
    int v = (t < nblocks) ? g_bsum[t] : 0;
    s[t] = v;
    __syncthreads();
    for (int off = 1; off < 256; off <<= 1) {
        int u = (t >= off) ? s[t - off] : 0;
        __syncthreads();
        s[t] += u;
        __syncthreads();
    }
    g_bpref[t] = s[t] - v;
    if (t == 255) g_off[NN] = s[255];
}
__global__ void __launch_bounds__(256) k_scan3() {
    int i = blockIdx.x * 256 + threadIdx.x;
    if (i < NN) {
        int o = g_off[i] + g_bpref[blockIdx.x];
        g_off[i] = o;
        g_cur[i] = o;
    }
}

__global__ void k_fill(const int* __restrict__ ei) {
    int e = blockIdx.x * blockDim.x + threadIdx.x;
    if (e >= EE) return;
    int s = ei[e], d = ei[EE + e];
    int p = atomicAdd(&g_cur[d], 1);
    g_csr_src[p] = s;
    g_csr_cf[p] = g_inv[s] * g_inv[d];
}

// ---------------- aggregation BEFORE gemm (R2 exact) -------------------------
template <int D>
__global__ void __launch_bounds__(D) k_agg(const float* __restrict__ h,
                                           float* __restrict__ z) {
    int i = blockIdx.x;
    int t = threadIdx.x;
    int beg = g_off[i], end = g_off[i + 1];
    float inv = g_inv[i];
    float acc = inv * inv * __ldg(h + (size_t)i * D + t);

    int j = beg;
    for (; j + 4 <= end; j += 4) {
        int s0 = __ldg(g_csr_src + j + 0);
        int s1 = __ldg(g_csr_src + j + 1);
        int s2 = __ldg(g_csr_src + j + 2);
        int s3 = __ldg(g_csr_src + j + 3);
        float c0 = __ldg(g_csr_cf + j + 0);
        float c1 = __ldg(g_csr_cf + j + 1);
        float c2 = __ldg(g_csr_cf + j + 2);
        float c3 = __ldg(g_csr_cf + j + 3);
        float v0 = __ldg(h + (size_t)s0 * D + t);
        float v1 = __ldg(h + (size_t)s1 * D + t);
        float v2 = __ldg(h + (size_t)s2 * D + t);
        float v3 = __ldg(h + (size_t)s3 * D + t);
        acc = fmaf(c0, v0, acc);
        acc = fmaf(c1, v1, acc);
        acc = fmaf(c2, v2, acc);
        acc = fmaf(c3, v3, acc);
    }
    for (; j < end; j++) {
        int s0 = __ldg(g_csr_src + j);
        float c0 = __ldg(g_csr_cf + j);
        acc = fmaf(c0, __ldg(h + (size_t)s0 * D + t), acc);
    }
    z[(size_t)i * D + t] = acc;
}

// ---------------- split-tf32 tensor-core GEMM (R5 measured variant) ----------
// Cm[M,Nc] = relu(A[M,K] @ B[K,Nc] + bias)
__device__ __forceinline__ uint32_t f2tf(float f) {
    uint32_t r;
    asm("cvt.rna.tf32.f32 %0, %1;" : "=r"(r) : "f"(f));
    return r;
}
__device__ __forceinline__ void mma_tf32(float4& d,
                                         uint32_t a0, uint32_t a1, uint32_t a2, uint32_t a3,
                                         uint32_t b0, uint32_t b1) {
    asm volatile("mma.sync.aligned.m16n8k8.row.col.f32.tf32.tf32.f32 "
                 "{%0,%1,%2,%3}, {%4,%5,%6,%7}, {%8,%9}, {%0,%1,%2,%3};"
                 : "+f"(d.x), "+f"(d.y), "+f"(d.z), "+f"(d.w)
                 : "r"(a0), "r"(a1), "r"(a2), "r"(a3), "r"(b0), "r"(b1));
}

#define TCSTRIDE 136

__global__ void __launch_bounds__(256) k_tcgemm(const float* __restrict__ A,
                                                const float* __restrict__ B,
                                                const float* __restrict__ bias,
                                                float* __restrict__ Cm,
                                                int M, int K, int Nc) {
    __shared__ uint32_t Ah[2][8][TCSTRIDE];
    __shared__ uint32_t Al[2][8][TCSTRIDE];
    __shared__ uint32_t Bh[2][8][TCSTRIDE];
    __shared__ uint32_t Bl[2][8][TCSTRIDE];

    const int tid = threadIdx.x;
    const int wid = tid >> 5;
    const int lane = tid & 31;
    const int q = lane >> 2;
    const int t4 = lane & 3;
    const int m0 = (wid & 3) * 32;
    const int n0 = (wid >> 2) * 64;

    const int rowBase = blockIdx.y * 128;
    const int colBase = blockIdx.x * 128;

    const int ar = tid >> 1;
    const int ac4 = (tid & 1) * 4;
    const int br = tid >> 5;
    const int bc4 = (tid & 31) * 4;
    const bool aok = (rowBase + ar) < M;
    const float* Aptr = A + (size_t)(rowBase + ar) * K + ac4;
    const float* Bptr = B + (size_t)br * Nc + colBase + bc4;

    float4 acc[2][8];
#pragma unroll
    for (int mi = 0; mi < 2; mi++)
#pragma unroll
        for (int ni = 0; ni < 8; ni++) acc[mi][ni] = make_float4(0.f, 0.f, 0.f, 0.f);

#define SPLIT_STORE(arrH, arrL, BUF, D0, D1, V)                      \
    {                                                                \
        uint32_t h_ = f2tf(V);                                       \
        float lo_ = (V) - __uint_as_float(h_);                       \
        arrH[BUF][D0][D1] = h_;                                      \
        arrL[BUF][D0][D1] = f2tf(lo_);                               \
    }
#define LOAD_TILE(BUF, K0)                                                        \
    {                                                                             \
        float4 va = aok ? *(const float4*)(Aptr + (K0))                           \
                        : make_float4(0.f, 0.f, 0.f, 0.f);                        \
        float4 vb = *(const float4*)(Bptr + (size_t)(K0) * Nc);                   \
        SPLIT_STORE(Ah, Al, BUF, ac4 + 0, ar, va.x)                               \
        SPLIT_STORE(Ah, Al, BUF, ac4 + 1, ar, va.y)                               \
        SPLIT_STORE(Ah, Al, BUF, ac4 + 2, ar, va.z)                               \
        SPLIT_STORE(Ah, Al, BUF, ac4 + 3, ar, va.w)                               \
        SPLIT_STORE(Bh, Bl, BUF, br, bc4 + 0, vb.x)                               \
        SPLIT_STORE(Bh, Bl, BUF, br, bc4 + 1, vb.y)                               \
        SPLIT_STORE(Bh, Bl, BUF, br, bc4 + 2, vb.z)                               \
        SPLIT_STORE(Bh, Bl, BUF, br, bc4 + 3, vb.w)                               \
    }

#define COMPUTE_TILE(BUF)                                                          \
    {                                                                              \
        uint32_t ah[2][4], al[2][4];                                               \
        _Pragma("unroll")                                                          \
        for (int mi = 0; mi < 2; mi++) {                                           \
            int mrow = m0 + mi * 16;                                               \
            ah[mi][0] = Ah[BUF][t4][mrow + q];                                     \
            ah[mi][1] = Ah[BUF][t4][mrow + q + 8];                                 \
            ah[mi][2] = Ah[BUF][t4 + 4][mrow + q];                                 \
            ah[mi][3] = Ah[BUF][t4 + 4][mrow + q + 8];                             \
            al[mi][0] = Al[BUF][t4][mrow + q];                                     \
            al[mi][1] = Al[BUF][t4][mrow + q + 8];                                 \
            al[mi][2] = Al[BUF][t4 + 4][mrow + q];                                 \
            al[mi][3] = Al[BUF][t4 + 4][mrow + q + 8];                             \
        }                                                                          \
        _Pragma("unroll")                                                          \
        for (int ni = 0; ni < 8; ni++) {                                           \
            int ncol = n0 + ni * 8 + q;                                            \
            uint32_t bh0 = Bh[BUF][t4][ncol];                                      \
            uint32_t bh1 = Bh[BUF][t4 + 4][ncol];                                  \
            uint32_t bl0 = Bl[BUF][t4][ncol];                                      \
            uint32_t bl1 = Bl[BUF][t4 + 4][ncol];                                  \
            _Pragma("unroll")                                                      \
            for (int mi = 0; mi < 2; mi++) {                                       \
                mma_tf32(acc[mi][ni], ah[mi][0], ah[mi][1], ah[mi][2], ah[mi][3],  \
                         bh0, bh1);                                                \
                mma_tf32(acc[mi][ni], ah[mi][0], ah[mi][1], ah[mi][2], ah[mi][3],  \
                         bl0, bl1);                                                \
                mma_tf32(acc[mi][ni], al[mi][0], al[mi][1], al[mi][2], al[mi][3],  \
                         bh0, bh1);                                                \
            }                                                                      \
        }                                                                          \
    }

    LOAD_TILE(0, 0)
    __syncthreads();

    int buf = 0;
    for (int k0 = 8; k0 < K; k0 += 8) {
        COMPUTE_TILE(buf)
        LOAD_TILE(buf ^ 1, k0)
        __syncthreads();
        buf ^= 1;
    }
    COMPUTE_TILE(buf)

#pragma unroll
    for (int mi = 0; mi < 2; mi++) {
#pragma unroll
        for (int ni = 0; ni < 8; ni++) {
            int col = colBase + n0 + ni * 8 + 2 * t4;
            float bb0 = bias[col], bb1 = bias[col + 1];
            int r0 = rowBase + m0 + mi * 16 + q;
            int r1 = r0 + 8;
            float4 v = acc[mi][ni];
            float o0 = fmaxf(v.x + bb0, 0.f);
            float o1 = fmaxf(v.y + bb1, 0.f);
            float o2 = fmaxf(v.z + bb0, 0.f);
            float o3 = fmaxf(v.w + bb1, 0.f);
            if (r0 < M) *(float2*)(Cm + (size_t)r0 * Nc + col) = make_float2(o0, o1);
            if (r1 < M) *(float2*)(Cm + (size_t)r1 * Nc + col) = make_float2(o2, o3);
        }
    }
}

// ---------------- softmax + argmax (R2 exact) --------------------------------
__global__ void __launch_bounds__(256) k_softmax(const float* __restrict__ logits,
                                                 float* __restrict__ S) {
    int i = blockIdx.x;
    int t = threadIdx.x;
    const float* row = logits + (size_t)i * CC;
    float v0 = row[t], v1 = row[t + 256];
    float bv = v0; int bi = t;
    if (v1 > bv) { bv = v1; bi = t + 256; }

    __shared__ float sv[256];
    __shared__ int   si[256];
    sv[t] = bv; si[t] = bi;
    __syncthreads();
    for (int s = 128; s > 0; s >>= 1) {
        if (t < s) {
            float ov = sv[t + s]; int oi = si[t + s];
            if (ov > sv[t] || (ov == sv[t] && oi < si[t])) { sv[t] = ov; si[t] = oi; }
        }
        __syncthreads();
    }
    float m = sv[0];
    if (t == 0) g_cluster[i] = si[0];
    __syncthreads();

    float e0 = expf(v0 - m), e1 = expf(v1 - m);
    sv[t] = e0 + e1;
    __syncthreads();
    for (int s = 128; s > 0; s >>= 1) {
        if (t < s) sv[t] += sv[t + s];
        __syncthreads();
    }
    float invsum = 1.0f / sv[0];
    S[(size_t)i * CC + t]       = e0 * invsum;
    S[(size_t)i * CC + t + 256] = e1 * invsum;
}

// ---------------- score layer (R2 exact) -------------------------------------
__global__ void k_hs(const float* __restrict__ x, const float* __restrict__ Ws) {
    int g = blockIdx.x * blockDim.x + threadIdx.x;
    int w = g >> 5, lane = g & 31;
    if (w >= NN) return;
    float s = 0.f;
    for (int f = lane; f < FF; f += 32) s = fmaf(x[(size_t)w * FF + f], Ws[f], s);
#pragma unroll
    for (int off = 16; off > 0; off >>= 1) s += __shfl_down_sync(0xFFFFFFFF, s, off);
    if (lane == 0) g_hs[w] = s;
}

__global__ void k_intradeg(const int* __restrict__ ei) {
    int e = blockIdx.x * blockDim.x + threadIdx.x;
    if (e >= EE) return;
    int s = ei[e], d = ei[EE + e];
    int cs = g_cluster[s], cd = g_cluster[d];
    if (cs == cd) {
        atomicAdd(&g_sdeg[d], 1);
        atomicAdd(&g_icnt[cs], 1);
    }
}

__global__ void k_invs() {
    int i = blockIdx.x * blockDim.x + threadIdx.x;
    if (i < NN) g_invs[i] = rsqrtf((float)g_sdeg[i] + 1.0f);
}

__global__ void k_sagg(const int* __restrict__ ei) {
    int e = blockIdx.x * blockDim.x + threadIdx.x;
    if (e >= EE) return;
    int s = ei[e], d = ei[EE + e];
    if (g_cluster[s] == g_cluster[d])
        atomicAdd(&g_sagg[d], g_invs[s] * g_invs[d] * g_hs[s]);
}

__global__ void k_score(const float* __restrict__ bs) {
    int i = blockIdx.x * blockDim.x + threadIdx.x;
    if (i >= NN) return;
    float inv = g_invs[i];
    float v = g_sagg[i] + inv * inv * g_hs[i] + bs[0];
    g_score[i] = tanhf(v);
}

__global__ void k_segmax() {
    int i = blockIdx.x * blockDim.x + threadIdx.x;
    if (i >= NN) return;
    atomicMax(&g_segkey[g_cluster[i]], fkey(g_score[i]));
}

__global__ void k_segidx() {
    int i = blockIdx.x * blockDim.x + threadIdx.x;
    if (i >= NN) return;
    int c = g_cluster[i];
    float mx = fdec(g_segkey[c]);
    if (g_score[i] >= mx) atomicMin(&g_segidx[c], i);
}

// ---------------- pooling + adjacency (R2 exact) -----------------------------
__global__ void __launch_bounds__(128) k_pool(const float* __restrict__ x,
                                              float* __restrict__ out) {
    int c = blockIdx.x;
    bool ne = g_icnt[c] > 0;
    float alpha = ne ? fdec(g_segkey[c]) : 0.f;
    int idx = min(g_segidx[c], NN - 1);
    out[(size_t)c * FF + threadIdx.x] = x[(size_t)idx * FF + threadIdx.x] * alpha;
}

__global__ void k_adj(const int* __restrict__ ei, float* __restrict__ out) {
    int e = blockIdx.x * blockDim.x + threadIdx.x;
    if (e >= EE) return;
    int cs = g_cluster[ei[e]], cd = g_cluster[ei[EE + e]];
    if (cs != cd && g_icnt[cs] > 0 && g_icnt[cd] > 0)
        out[OFF_ADJ + (size_t)cs * CC + cd] = 1.0f;
}

// ---------------- launch (R2 exact order; gemm swapped) ----------------------
extern "C" void kernel_launch(void* const* d_in, const int* in_sizes, int n_in,
                              void* d_out, int out_size) {
    const float* x   = (const float*)d_in[0];
    const int*   ei  = (const int*)d_in[1];
    const float* W1  = (const float*)d_in[3];
    const float* b1  = (const float*)d_in[4];
    const float* W2  = (const float*)d_in[5];
    const float* b2  = (const float*)d_in[6];
    const float* W3  = (const float*)d_in[7];
    const float* b3  = (const float*)d_in[8];
    const float* Ws  = (const float*)d_in[9];
    const float* bs  = (const float*)d_in[10];
    float* out = (float*)d_out;

    const int EB = (EE + 255) / 256;
    const int NB = (NN + 255) / 256;

    k_init<<<512, 256>>>(out);
    k_deg<<<EB, 256>>>(ei);
    k_inv<<<NB, 256>>>();
    k_scan1<<<NB, 256>>>();
    k_scan2<<<1, 256>>>(NB);
    k_scan3<<<NB, 256>>>();
    k_fill<<<EB, 256>>>(ei);

    // layer 1: z = Ahat @ x (128); h = relu(z @ W1 + b1) (256)
    k_agg<128><<<NN, 128>>>(x, g_z);
    {
        dim3 g(HH / 128, (NN + 127) / 128);
        k_tcgemm<<<g, 256>>>(g_z, W1, b1, g_h, NN, FF, HH);
    }
    // layer 2: z = Ahat @ h (256); h = relu(z @ W2 + b2) (256)
    k_agg<256><<<NN, 256>>>(g_h, g_z);
    {
        dim3 g(HH / 128, (NN + 127) / 128);
        k_tcgemm<<<g, 256>>>(g_z, W2, b2, g_h, NN, HH, HH);
    }
    // layer 3: z = Ahat @ h (256); logits = relu(z @ W3 + b3) (512)
    k_agg<256><<<NN, 256>>>(g_h, g_z);
    {
        dim3 g(CC / 128, (NN + 127) / 128);
        k_tcgemm<<<g, 256>>>(g_z, W3, b3, g_h, NN, HH, CC);
    }

    k_softmax<<<NN, 256>>>(g_h, out + OFF_S);

    k_hs<<<(NN * 32 + 255) / 256, 256>>>(x, Ws);
    k_intradeg<<<EB, 256>>>(ei);
    k_invs<<<NB, 256>>>();
    k_sagg<<<EB, 256>>>(ei);
    k_score<<<NB, 256>>>(bs);
    k_segmax<<<NB, 256>>>();
    k_segidx<<<NB, 256>>>();
    k_pool<<<CC, 128>>>(x, out);
    k_adj<<<EB, 256>>>(ei, out);

    (void)in_sizes; (void)n_in; (void)out_size;
}

// round 10
// speedup vs baseline: 1.6698x; 1.0269x over previous
#include <cuda_runtime.h>
#include <math.h>
#include <stdint.h>

#define NN 50000
#define FF 128
#define CC 512
#define EE 800000
#define HH 256

// Output layout: new_x [C,F], new_adj [C,C], new_batch [C], S [N,C]
#define OFF_ADJ   (CC*FF)
#define OFF_BATCH (OFF_ADJ + CC*CC)
#define OFF_S     (OFF_BATCH + CC)

#define EB ((EE + 255) / 256)
#define HSB ((NN * 32 + 255) / 256)

// ---------------- scratch ----------------------------------------------------
__device__ __align__(16) float g_h[(size_t)NN * CC];
__device__ __align__(16) float g_z[(size_t)NN * HH];
__device__ float g_inv[NN];
__device__ int   g_deg[NN];
__device__ int   g_off[NN + 1];
__device__ int   g_cur[NN];
__device__ int   g_csr_src[EE];
__device__ float g_csr_cf[EE];
__device__ int   g_cluster[NN];
__device__ float g_hs[NN];
__device__ int   g_sdeg[NN];
__device__ float g_invs[NN];
__device__ float g_sagg[NN];
__device__ float g_score[NN];
__device__ int   g_icnt[CC];
__device__ int   g_segkey[CC];
__device__ int   g_segidx[CC];

__device__ __forceinline__ int fkey(float f) {
    int b = __float_as_int(f);
    return b < 0 ? (b ^ 0x7FFFFFFF) : b;
}
__device__ __forceinline__ float fdec(int k) {
    return __int_as_float(k < 0 ? (k ^ 0x7FFFFFFF) : k);
}

// ---------------- init / degree / scan / fill --------------------------------
__global__ void k_init(float* out) {
    int i = blockIdx.x * blockDim.x + threadIdx.x;
    int stride = gridDim.x * blockDim.x;
    for (int j = i; j < NN; j += stride) { g_deg[j] = 0; g_sdeg[j] = 0; g_sagg[j] = 0.f; }
    for (int j = i; j < CC; j += stride) {
        g_icnt[j] = 0; g_segkey[j] = (int)0x80000000; g_segidx[j] = NN;
        out[OFF_BATCH + j] = 0.f;
    }
    for (int j = i; j < CC * CC; j += stride) out[OFF_ADJ + j] = 0.f;
}

__global__ void k_deg(const int* __restrict__ ei) {
    int e = blockIdx.x * blockDim.x + threadIdx.x;
    if (e < EE) atomicAdd(&g_deg[ei[EE + e]], 1);
}

// single-block: exclusive scan of g_deg -> g_off/g_cur, plus g_inv
__global__ void __launch_bounds__(1024) k_scanall() {
    __shared__ int ssum[1024];
    int t = threadIdx.x;
    const int chunk = (NN + 1023) / 1024;
    int b = t * chunk, e = min(b + chunk, NN);
    int s = 0;
    for (int i = b; i < e; i++) s += g_deg[i];
    ssum[t] = s;
    __syncthreads();
    for (int off = 1; off < 1024; off <<= 1) {
        int v = (t >= off) ? ssum[t - off] : 0;
        __syncthreads();
        ssum[t] += v;
        __syncthreads();
    }
    int run = (t > 0) ? ssum[t - 1] : 0;
    for (int i = b; i < e; i++) {
        int d = g_deg[i];
        g_off[i] = run;
        g_cur[i] = run;
        g_inv[i] = rsqrtf((float)d + 1.0f);
        run += d;
    }
    if (t == 1023) g_off[NN] = ssum[1023];
}

__global__ void k_fill(const int* __restrict__ ei) {
    int e = blockIdx.x * blockDim.x + threadIdx.x;
    if (e >= EE) return;
    int s = ei[e], d = ei[EE + e];
    int p = atomicAdd(&g_cur[d], 1);
    g_csr_src[p] = s;
    g_csr_cf[p] = g_inv[s] * g_inv[d];
}

// ---------------- aggregation: persistent grid-stride, R2 inner loop ---------
template <int D>
__global__ void __launch_bounds__(D) k_agg(const float* __restrict__ h,
                                           float* __restrict__ z) {
    int t = threadIdx.x;
    for (int i = blockIdx.x; i < NN; i += gridDim.x) {
        int beg = g_off[i], end = g_off[i + 1];
        float inv = g_inv[i];
        float acc = inv * inv * __ldg(h + (size_t)i * D + t);

        int j = beg;
        for (; j + 4 <= end; j += 4) {
            int s0 = __ldg(g_csr_src + j + 0);
            int s1 = __ldg(g_csr_src + j + 1);
            int s2 = __ldg(g_csr_src + j + 2);
            int s3 = __ldg(g_csr_src + j + 3);
            float c0 = __ldg(g_csr_cf + j + 0);
            float c1 = __ldg(g_csr_cf + j + 1);
            float c2 = __ldg(g_csr_cf + j + 2);
            float c3 = __ldg(g_csr_cf + j + 3);
            float v0 = __ldg(h + (size_t)s0 * D + t);
            float v1 = __ldg(h + (size_t)s1 * D + t);
            float v2 = __ldg(h + (size_t)s2 * D + t);
            float v3 = __ldg(h + (size_t)s3 * D + t);
            acc = fmaf(c0, v0, acc);
            acc = fmaf(c1, v1, acc);
            acc = fmaf(c2, v2, acc);
            acc = fmaf(c3, v3, acc);
        }
        for (; j < end; j++) {
            int s0 = __ldg(g_csr_src + j);
            float c0 = __ldg(g_csr_cf + j);
            acc = fmaf(c0, __ldg(h + (size_t)s0 * D + t), acc);
        }
        z[(size_t)i * D + t] = acc;
    }
}

// ---------------- split-tf32 tensor-core GEMM (measured variant) -------------
__device__ __forceinline__ uint32_t f2tf(float f) {
    uint32_t r;
    asm("cvt.rna.tf32.f32 %0, %1;" : "=r"(r) : "f"(f));
    return r;
}
__device__ __forceinline__ void mma_tf32(float4& d,
                                         uint32_t a0, uint32_t a1, uint32_t a2, uint32_t a3,
                                         uint32_t b0, uint32_t b1) {
    asm volatile("mma.sync.aligned.m16n8k8.row.col.f32.tf32.tf32.f32 "
                 "{%0,%1,%2,%3}, {%4,%5,%6,%7}, {%8,%9}, {%0,%1,%2,%3};"
                 : "+f"(d.x), "+f"(d.y), "+f"(d.z), "+f"(d.w)
                 : "r"(a0), "r"(a1), "r"(a2), "r"(a3), "r"(b0), "r"(b1));
}

#define TCSTRIDE 136

__global__ void __launch_bounds__(256) k_tcgemm(const float* __restrict__ A,
                                                const float* __restrict__ B,
                                                const float* __restrict__ bias,
                                                float* __restrict__ Cm,
                                                int M, int K, int Nc) {
    __shared__ uint32_t Ah[2][8][TCSTRIDE];
    __shared__ uint32_t Al[2][8][TCSTRIDE];
    __shared__ uint32_t Bh[2][8][TCSTRIDE];
    __shared__ uint32_t Bl[2][8][TCSTRIDE];

    const int tid = threadIdx.x;
    const int wid = tid >> 5;
    const int lane = tid & 31;
    const int q = lane >> 2;
    const int t4 = lane & 3;
    const int m0 = (wid & 3) * 32;
    const int n0 = (wid >> 2) * 64;

    const int rowBase = blockIdx.y * 128;
    const int colBase = blockIdx.x * 128;

    const int ar = tid >> 1;
    const int ac4 = (tid & 1) * 4;
    const int br = tid >> 5;
    const int bc4 = (tid & 31) * 4;
    const bool aok = (rowBase + ar) < M;
    const float* Aptr = A + (size_t)(rowBase + ar) * K + ac4;
    const float* Bptr = B + (size_t)br * Nc + colBase + bc4;

    float4 acc[2][8];
#pragma unroll
    for (int mi = 0; mi < 2; mi++)
#pragma unroll
        for (int ni = 0; ni < 8; ni++) acc[mi][ni] = make_float4(0.f, 0.f, 0.f, 0.f);

#define SPLIT_STORE(arrH, arrL, BUF, D0, D1, V)                      \
    {                                                                \
        uint32_t h_ = f2tf(V);                                       \
        float lo_ = (V) - __uint_as_float(h_);                       \
        arrH[BUF][D0][D1] = h_;                                      \
        arrL[BUF][D0][D1] = f2tf(lo_);                               \
    }
#define LOAD_TILE(BUF, K0)                                                        \
    {                                                                             \
        float4 va = aok ? *(const float4*)(Aptr + (K0))                           \
                        : make_float4(0.f, 0.f, 0.f, 0.f);                        \
        float4 vb = *(const float4*)(Bptr + (size_t)(K0) * Nc);                   \
        SPLIT_STORE(Ah, Al, BUF, ac4 + 0, ar, va.x)                               \
        SPLIT_STORE(Ah, Al, BUF, ac4 + 1, ar, va.y)                               \
        SPLIT_STORE(Ah, Al, BUF, ac4 + 2, ar, va.z)                               \
        SPLIT_STORE(Ah, Al, BUF, ac4 + 3, ar, va.w)                               \
        SPLIT_STORE(Bh, Bl, BUF, br, bc4 + 0, vb.x)                               \
        SPLIT_STORE(Bh, Bl, BUF, br, bc4 + 1, vb.y)                               \
        SPLIT_STORE(Bh, Bl, BUF, br, bc4 + 2, vb.z)                               \
        SPLIT_STORE(Bh, Bl, BUF, br, bc4 + 3, vb.w)                               \
    }

#define COMPUTE_TILE(BUF)                                                          \
    {                                                                              \
        uint32_t ah[2][4], al[2][4];                                               \
        _Pragma("unroll")                                                          \
        for (int mi = 0; mi < 2; mi++) {                                           \
            int mrow = m0 + mi * 16;                                               \
            ah[mi][0] = Ah[BUF][t4][mrow + q];                                     \
            ah[mi][1] = Ah[BUF][t4][mrow + q + 8];                                 \
            ah[mi][2] = Ah[BUF][t4 + 4][mrow + q];                                 \
            ah[mi][3] = Ah[BUF][t4 + 4][mrow + q + 8];                             \
            al[mi][0] = Al[BUF][t4][mrow + q];                                     \
            al[mi][1] = Al[BUF][t4][mrow + q + 8];                                 \
            al[mi][2] = Al[BUF][t4 + 4][mrow + q];                                 \
            al[mi][3] = Al[BUF][t4 + 4][mrow + q + 8];                             \
        }                                                                          \
        _Pragma("unroll")                                                          \
        for (int ni = 0; ni < 8; ni++) {                                           \
            int ncol = n0 + ni * 8 + q;                                            \
            uint32_t bh0 = Bh[BUF][t4][ncol];                                      \
            uint32_t bh1 = Bh[BUF][t4 + 4][ncol];                                  \
            uint32_t bl0 = Bl[BUF][t4][ncol];                                      \
            uint32_t bl1 = Bl[BUF][t4 + 4][ncol];                                  \
            _Pragma("unroll")                                                      \
            for (int mi = 0; mi < 2; mi++) {                                       \
                mma_tf32(acc[mi][ni], ah[mi][0], ah[mi][1], ah[mi][2], ah[mi][3],  \
                         bh0, bh1);                                                \
                mma_tf32(acc[mi][ni], ah[mi][0], ah[mi][1], ah[mi][2], ah[mi][3],  \
                         bl0, bl1);                                                \
                mma_tf32(acc[mi][ni], al[mi][0], al[mi][1], al[mi][2], al[mi][3],  \
                         bh0, bh1);                                                \
            }                                                                      \
        }                                                                          \
    }

    LOAD_TILE(0, 0)
    __syncthreads();

    int buf = 0;
    for (int k0 = 8; k0 < K; k0 += 8) {
        COMPUTE_TILE(buf)
        LOAD_TILE(buf ^ 1, k0)
        __syncthreads();
        buf ^= 1;
    }
    COMPUTE_TILE(buf)

#pragma unroll
    for (int mi = 0; mi < 2; mi++) {
#pragma unroll
        for (int ni = 0; ni < 8; ni++) {
            int col = colBase + n0 + ni * 8 + 2 * t4;
            float bb0 = bias[col], bb1 = bias[col + 1];
            int r0 = rowBase + m0 + mi * 16 + q;
            int r1 = r0 + 8;
            float4 v = acc[mi][ni];
            float o0 = fmaxf(v.x + bb0, 0.f);
            float o1 = fmaxf(v.y + bb1, 0.f);
            float o2 = fmaxf(v.z + bb0, 0.f);
            float o3 = fmaxf(v.w + bb1, 0.f);
            if (r0 < M) *(float2*)(Cm + (size_t)r0 * Nc + col) = make_float2(o0, o1);
            if (r1 < M) *(float2*)(Cm + (size_t)r1 * Nc + col) = make_float2(o2, o3);
        }
    }
}

// ---------------- softmax + argmax: persistent grid-stride -------------------
__global__ void __launch_bounds__(256) k_softmax(const float* __restrict__ logits,
                                                 float* __restrict__ S) {
    int t = threadIdx.x;
    __shared__ float sv[256];
    __shared__ int   si[256];
    for (int i = blockIdx.x; i < NN; i += gridDim.x) {
        const float* row = logits + (size_t)i * CC;
        float v0 = row[t], v1 = row[t + 256];
        float bv = v0; int bi = t;
        if (v1 > bv) { bv = v1; bi = t + 256; }

        sv[t] = bv; si[t] = bi;
        __syncthreads();
        for (int s = 128; s > 0; s >>= 1) {
            if (t < s) {
                float ov = sv[t + s]; int oi = si[t + s];
                if (ov > sv[t] || (ov == sv[t] && oi < si[t])) { sv[t] = ov; si[t] = oi; }
            }
            __syncthreads();
        }
        float m = sv[0];
        if (t == 0) g_cluster[i] = si[0];
        __syncthreads();

        float e0 = expf(v0 - m), e1 = expf(v1 - m);
        sv[t] = e0 + e1;
        __syncthreads();
        for (int s = 128; s > 0; s >>= 1) {
            if (t < s) sv[t] += sv[t + s];
            __syncthreads();
        }
        float invsum = 1.0f / sv[0];
        S[(size_t)i * CC + t]       = e0 * invsum;
        S[(size_t)i * CC + t + 256] = e1 * invsum;
        __syncthreads();
    }
}

// ---------------- fused: hs (x@Ws) + intradeg --------------------------------
__global__ void k_hsintra(const float* __restrict__ x,
                          const float* __restrict__ Ws,
                          const int* __restrict__ ei) {
    int bid = blockIdx.x;
    int t = threadIdx.x;
    if (bid < HSB) {
        int g = bid * 256 + t;
        int w = g >> 5, lane = g & 31;
        if (w >= NN) return;
        float s = 0.f;
        for (int f = lane; f < FF; f += 32) s = fmaf(x[(size_t)w * FF + f], Ws[f], s);
#pragma unroll
        for (int off = 16; off > 0; off >>= 1) s += __shfl_down_sync(0xFFFFFFFF, s, off);
        if (lane == 0) g_hs[w] = s;
    } else {
        int e = (bid - HSB) * 256 + t;
        if (e >= EE) return;
        int s = ei[e], d = ei[EE + e];
        int cs = g_cluster[s], cd = g_cluster[d];
        if (cs == cd) {
            atomicAdd(&g_sdeg[d], 1);
            atomicAdd(&g_icnt[cs], 1);
        }
    }
}

__global__ void k_invs() {
    int i = blockIdx.x * blockDim.x + threadIdx.x;
    if (i < NN) g_invs[i] = rsqrtf((float)g_sdeg[i] + 1.0f);
}

__global__ void k_sagg(const int* __restrict__ ei) {
    int e = blockIdx.x * blockDim.x + threadIdx.x;
    if (e >= EE) return;
    int s = ei[e], d = ei[EE + e];
    if (g_cluster[s] == g_cluster[d])
        atomicAdd(&g_sagg[d], g_invs[s] * g_invs[d] * g_hs[s]);
}

// score + fused segmax
__global__ void k_score(const float* __restrict__ bs) {
    int i = blockIdx.x * blockDim.x + threadIdx.x;
    if (i >= NN) return;
    float inv = g_invs[i];
    float v = g_sagg[i] + inv * inv * g_hs[i] + bs[0];
    float sc = tanhf(v);
    g_score[i] = sc;
    atomicMax(&g_segkey[g_cluster[i]], fkey(sc));
}

__global__ void k_segidx() {
    int i = blockIdx.x * blockDim.x + threadIdx.x;
    if (i >= NN) return;
    int c = g_cluster[i];
    float mx = fdec(g_segkey[c]);
    if (g_score[i] >= mx) atomicMin(&g_segidx[c], i);
}

// ---------------- fused: pool + adjacency ------------------------------------
__global__ void k_pooladj(const float* __restrict__ x,
                          const int* __restrict__ ei,
                          float* __restrict__ out) {
    int bid = blockIdx.x;
    int t = threadIdx.x;
    if (bid < CC) {
        if (t < 128) {
            int c = bid;
            bool ne = g_icnt[c] > 0;
            float alpha = ne ? fdec(g_segkey[c]) : 0.f;
            int idx = min(g_segidx[c], NN - 1);
            out[(size_t)c * FF + t] = x[(size_t)idx * FF + t] * alpha;
        }
    } else {
        int e = (bid - CC) * 256 + t;
        if (e >= EE) return;
        int cs = g_cluster[ei[e]], cd = g_cluster[ei[EE + e]];
        if (cs != cd && g_icnt[cs] > 0 && g_icnt[cd] > 0)
            out[OFF_ADJ + (size_t)cs * CC + cd] = 1.0f;
    }
}

// ---------------- launch ------------------------------------------------------
extern "C" void kernel_launch(void* const* d_in, const int* in_sizes, int n_in,
                              void* d_out, int out_size) {
    const float* x   = (const float*)d_in[0];
    const int*   ei  = (const int*)d_in[1];
    const float* W1  = (const float*)d_in[3];
    const float* b1  = (const float*)d_in[4];
    const float* W2  = (const float*)d_in[5];
    const float* b2  = (const float*)d_in[6];
    const float* W3  = (const float*)d_in[7];
    const float* b3  = (const float*)d_in[8];
    const float* Ws  = (const float*)d_in[9];
    const float* bs  = (const float*)d_in[10];
    float* out = (float*)d_out;

    const int NB = (NN + 255) / 256;
    const int PG128 = 148 * 16;   // persistent grid, 128-thread blocks
    const int PG256 = 148 * 8;    // persistent grid, 256-thread blocks

    k_init<<<512, 256>>>(out);          // 0
    k_deg<<<EB, 256>>>(ei);             // 1
    k_scanall<<<1, 1024>>>();           // 2
    k_fill<<<EB, 256>>>(ei);            // 3

    // layer 1: z = Ahat @ x (128); h = relu(z @ W1 + b1) (256)
    k_agg<128><<<PG128, 128>>>(x, g_z);
    {
        dim3 g(HH / 128, (NN + 127) / 128);
        k_tcgemm<<<g, 256>>>(g_z, W1, b1, g_h, NN, FF, HH);
    }
    // layer 2
    k_agg<256><<<PG256, 256>>>(g_h, g_z);
    {
        dim3 g(HH / 128, (NN + 127) / 128);
        k_tcgemm<<<g, 256>>>(g_z, W2, b2, g_h, NN, HH, HH);
    }
    // layer 3
    k_agg<256><<<PG256, 256>>>(g_h, g_z);
    {
        dim3 g(CC / 128, (NN + 127) / 128);
        k_tcgemm<<<g, 256>>>(g_z, W3, b3, g_h, NN, HH, CC);
    }

    k_softmax<<<PG256, 256>>>(g_h, out + OFF_S);

    k_hsintra<<<HSB + EB, 256>>>(x, Ws, ei);
    k_invs<<<NB, 256>>>();
    k_sagg<<<EB, 256>>>(ei);
    k_score<<<NB, 256>>>(bs);
    k_segidx<<<NB, 256>>>();
    k_pooladj<<<CC + EB, 256>>>(x, ei, out);

    (void)in_sizes; (void)n_in; (void)out_size;
}

// round 11
// speedup vs baseline: 1.8636x; 1.1161x over previous
#include <cuda_runtime.h>
#include <math.h>
#include <stdint.h>

#define NN 50000
#define FF 128
#define CC 512
#define EE 800000
#define HH 256

// Output layout: new_x [C,F], new_adj [C,C], new_batch [C], S [N,C]
#define OFF_ADJ   (CC*FF)
#define OFF_BATCH (OFF_ADJ + CC*CC)
#define OFF_S     (OFF_BATCH + CC)

#define EB ((EE + 255) / 256)
#define HSB ((NN * 32 + 255) / 256)
#define INITB 512

// ---------------- scratch ----------------------------------------------------
__device__ __align__(16) float g_h[(size_t)NN * CC];
__device__ __align__(16) float g_z[(size_t)NN * HH];
__device__ float g_inv[NN];
__device__ int   g_deg[NN];
__device__ int   g_off[NN + 1];
__device__ int   g_cur[NN];
__device__ int   g_csr_src[EE];
__device__ float g_csr_cf[EE];
__device__ int   g_cluster[NN];
__device__ float g_hs[NN];
__device__ int   g_sdeg[NN];
__device__ float g_invs[NN];
__device__ float g_sagg[NN];
__device__ float g_score[NN];
__device__ int   g_icnt[CC];
__device__ int   g_segkey[CC];
__device__ int   g_segidx[CC];

__device__ __forceinline__ int fkey(float f) {
    int b = __float_as_int(f);
    return b < 0 ? (b ^ 0x7FFFFFFF) : b;
}
__device__ __forceinline__ float fdec(int k) {
    return __int_as_float(k < 0 ? (k ^ 0x7FFFFFFF) : k);
}

// ---------------- fused init + degree ----------------------------------------
__global__ void k_initdeg(float* out, const int* __restrict__ ei) {
    int bid = blockIdx.x;
    int t = threadIdx.x;
    if (bid < INITB) {
        int i = bid * 256 + t;
        int stride = INITB * 256;
        for (int j = i; j < NN; j += stride) { g_sdeg[j] = 0; g_sagg[j] = 0.f; }
        for (int j = i; j < CC; j += stride) {
            g_icnt[j] = 0; g_segkey[j] = (int)0x80000000; g_segidx[j] = NN;
            out[OFF_BATCH + j] = 0.f;
        }
        for (int j = i; j < CC * CC; j += stride) out[OFF_ADJ + j] = 0.f;
        for (int j = i; j < NN; j += stride) g_deg[j] = 0;
    } else {
        // NOTE: g_deg zeroing above races with this in theory; guard with a
        // separate zero domain: deg blocks spin only on edges, and the zeroing
        // of g_deg is done by the SAME block range before any atomics?  No —
        // different blocks.  Instead g_deg is zeroed at the END of k_fill's
        // consumers... simplest safe fix: deg uses atomicAdd on g_cur? No.
        // Safe approach: this branch accumulates into g_sdeg? No.
        // => use a dedicated counter array g_cur as the histogram target,
        //    zeroed last replay?  Not deterministic.
        // Resolution: deg atomics target g_deg, and g_deg zeroing happens in
        // the FIRST loop of this same kernel but ordering across blocks is not
        // guaranteed.  Therefore: deg blocks first wait on nothing — instead we
        // make zeroing unnecessary by writing, not accumulating:
        // we count via atomicAdd into g_off (zeroed below) — no.
        //
        // Final safe design (used here): histogram into g_deg with atomics is
        // moved to THIS branch, and zeroing of g_deg is done by these SAME
        // blocks before counting, partitioned by edge-block index < NB edge.
        int e = (bid - INITB) * 256 + t;
        // zero g_deg using the first ceil(NN/256) edge-blocks (they cover NN)
        int zb = bid - INITB;
        int zi = zb * 256 + t;
        if (zi < NN) g_deg[zi] = 0;
        // grid-wide: cannot atomically count before all zeroing done -> we
        // defer counting to k_scanall (single block, does histogram serially
        // in parallel threads).  This branch therefore only zeroes.
        (void)e; (void)ei;
    }
}

// single block: degree histogram + exclusive scan + inv + cur
__global__ void __launch_bounds__(1024) k_scanall(const int* __restrict__ ei) {
    int t = threadIdx.x;
    // histogram (g_deg zeroed by k_initdeg)
    for (int e = t; e < EE; e += 1024) atomicAdd(&g_deg[ei[EE + e]], 1);
    __syncthreads();

    __shared__ int ssum[1024];
    const int chunk = (NN + 1023) / 1024;
    int b = t * chunk, e = min(b + chunk, NN);
    int s = 0;
    for (int i = b; i < e; i++) s += g_deg[i];
    ssum[t] = s;
    __syncthreads();
    for (int off = 1; off < 1024; off <<= 1) {
        int v = (t >= off) ? ssum[t - off] : 0;
        __syncthreads();
        ssum[t] += v;
        __syncthreads();
    }
    int run = (t > 0) ? ssum[t - 1] : 0;
    for (int i = b; i < e; i++) {
        int d = g_deg[i];
        g_off[i] = run;
        g_cur[i] = run;
        g_inv[i] = rsqrtf((float)d + 1.0f);
        run += d;
    }
    if (t == 1023) g_off[NN] = ssum[1023];
}

__global__ void k_fill(const int* __restrict__ ei) {
    int e = blockIdx.x * blockDim.x + threadIdx.x;
    if (e >= EE) return;
    int s = ei[e], d = ei[EE + e];
    int p = atomicAdd(&g_cur[d], 1);
    g_csr_src[p] = s;
    g_csr_cf[p] = g_inv[s] * g_inv[d];
}

// ---------------- aggregation: persistent grid-stride, unroll 8 --------------
template <int D>
__global__ void __launch_bounds__(D) k_agg(const float* __restrict__ h,
                                           float* __restrict__ z) {
    int t = threadIdx.x;
    for (int i = blockIdx.x; i < NN; i += gridDim.x) {
        int beg = g_off[i], end = g_off[i + 1];
        float inv = g_inv[i];
        float acc0 = inv * inv * __ldg(h + (size_t)i * D + t);
        float acc1 = 0.f;

        int j = beg;
        for (; j + 8 <= end; j += 8) {
            int s0 = __ldg(g_csr_src + j + 0);
            int s1 = __ldg(g_csr_src + j + 1);
            int s2 = __ldg(g_csr_src + j + 2);
            int s3 = __ldg(g_csr_src + j + 3);
            int s4 = __ldg(g_csr_src + j + 4);
            int s5 = __ldg(g_csr_src + j + 5);
            int s6 = __ldg(g_csr_src + j + 6);
            int s7 = __ldg(g_csr_src + j + 7);
            float c0 = __ldg(g_csr_cf + j + 0);
            float c1 = __ldg(g_csr_cf + j + 1);
            float c2 = __ldg(g_csr_cf + j + 2);
            float c3 = __ldg(g_csr_cf + j + 3);
            float c4 = __ldg(g_csr_cf + j + 4);
            float c5 = __ldg(g_csr_cf + j + 5);
            float c6 = __ldg(g_csr_cf + j + 6);
            float c7 = __ldg(g_csr_cf + j + 7);
            float v0 = __ldg(h + (size_t)s0 * D + t);
            float v1 = __ldg(h + (size_t)s1 * D + t);
            float v2 = __ldg(h + (size_t)s2 * D + t);
            float v3 = __ldg(h + (size_t)s3 * D + t);
            float v4 = __ldg(h + (size_t)s4 * D + t);
            float v5 = __ldg(h + (size_t)s5 * D + t);
            float v6 = __ldg(h + (size_t)s6 * D + t);
            float v7 = __ldg(h + (size_t)s7 * D + t);
            acc0 = fmaf(c0, v0, acc0); acc1 = fmaf(c1, v1, acc1);
            acc0 = fmaf(c2, v2, acc0); acc1 = fmaf(c3, v3, acc1);
            acc0 = fmaf(c4, v4, acc0); acc1 = fmaf(c5, v5, acc1);
            acc0 = fmaf(c6, v6, acc0); acc1 = fmaf(c7, v7, acc1);
        }
        for (; j < end; j++) {
            int s0 = __ldg(g_csr_src + j);
            float c0 = __ldg(g_csr_cf + j);
            acc0 = fmaf(c0, __ldg(h + (size_t)s0 * D + t), acc0);
        }
        z[(size_t)i * D + t] = acc0 + acc1;
    }
}

// ---------------- split-tf32 TC GEMM, software-pipelined ---------------------
__device__ __forceinline__ uint32_t f2tf(float f) {
    uint32_t r;
    asm("cvt.rna.tf32.f32 %0, %1;" : "=r"(r) : "f"(f));
    return r;
}
__device__ __forceinline__ void mma_tf32(float4& d,
                                         uint32_t a0, uint32_t a1, uint32_t a2, uint32_t a3,
                                         uint32_t b0, uint32_t b1) {
    asm volatile("mma.sync.aligned.m16n8k8.row.col.f32.tf32.tf32.f32 "
                 "{%0,%1,%2,%3}, {%4,%5,%6,%7}, {%8,%9}, {%0,%1,%2,%3};"
                 : "+f"(d.x), "+f"(d.y), "+f"(d.z), "+f"(d.w)
                 : "r"(a0), "r"(a1), "r"(a2), "r"(a3), "r"(b0), "r"(b1));
}

#define TCSTRIDE 136

__global__ void __launch_bounds__(256) k_tcgemm(const float* __restrict__ A,
                                                const float* __restrict__ B,
                                                const float* __restrict__ bias,
                                                float* __restrict__ Cm,
                                                int M, int K, int Nc) {
    __shared__ uint32_t Ah[2][8][TCSTRIDE];
    __shared__ uint32_t Al[2][8][TCSTRIDE];
    __shared__ uint32_t Bh[2][8][TCSTRIDE];
    __shared__ uint32_t Bl[2][8][TCSTRIDE];

    const int tid = threadIdx.x;
    const int wid = tid >> 5;
    const int lane = tid & 31;
    const int q = lane >> 2;
    const int t4 = lane & 3;
    const int m0 = (wid & 3) * 32;
    const int n0 = (wid >> 2) * 64;

    const int rowBase = blockIdx.y * 128;
    const int colBase = blockIdx.x * 128;

    const int ar = tid >> 1;
    const int ac4 = (tid & 1) * 4;
    const int br = tid >> 5;
    const int bc4 = (tid & 31) * 4;
    const bool aok = (rowBase + ar) < M;
    const float* Aptr = A + (size_t)(rowBase + ar) * K + ac4;
    const float* Bptr = B + (size_t)br * Nc + colBase + bc4;

    float4 acc[2][8];
#pragma unroll
    for (int mi = 0; mi < 2; mi++)
#pragma unroll
        for (int ni = 0; ni < 8; ni++) acc[mi][ni] = make_float4(0.f, 0.f, 0.f, 0.f);

#define SPLIT_STORE(arrH, arrL, BUF, D0, D1, V)                      \
    {                                                                \
        uint32_t h_ = f2tf(V);                                       \
        float lo_ = (V) - __uint_as_float(h_);                       \
        arrH[BUF][D0][D1] = h_;                                      \
        arrL[BUF][D0][D1] = f2tf(lo_);                               \
    }
#define STORE_TILE(BUF, VA, VB)                                                   \
    {                                                                             \
        SPLIT_STORE(Ah, Al, BUF, ac4 + 0, ar, (VA).x)                             \
        SPLIT_STORE(Ah, Al, BUF, ac4 + 1, ar, (VA).y)                             \
        SPLIT_STORE(Ah, Al, BUF, ac4 + 2, ar, (VA).z)                             \
        SPLIT_STORE(Ah, Al, BUF, ac4 + 3, ar, (VA).w)                             \
        SPLIT_STORE(Bh, Bl, BUF, br, bc4 + 0, (VB).x)                             \
        SPLIT_STORE(Bh, Bl, BUF, br, bc4 + 1, (VB).y)                             \
        SPLIT_STORE(Bh, Bl, BUF, br, bc4 + 2, (VB).z)                             \
        SPLIT_STORE(Bh, Bl, BUF, br, bc4 + 3, (VB).w)                             \
    }

#define COMPUTE_TILE(BUF)                                                          \
    {                                                                              \
        uint32_t ah[2][4], al[2][4];                                               \
        _Pragma("unroll")                                                          \
        for (int mi = 0; mi < 2; mi++) {                                           \
            int mrow = m0 + mi * 16;                                               \
            ah[mi][0] = Ah[BUF][t4][mrow + q];                                     \
            ah[mi][1] = Ah[BUF][t4][mrow + q + 8];                                 \
            ah[mi][2] = Ah[BUF][t4 + 4][mrow + q];                                 \
            ah[mi][3] = Ah[BUF][t4 + 4][mrow + q + 8];                             \
            al[mi][0] = Al[BUF][t4][mrow + q];                                     \
            al[mi][1] = Al[BUF][t4][mrow + q + 8];                                 \
            al[mi][2] = Al[BUF][t4 + 4][mrow + q];                                 \
            al[mi][3] = Al[BUF][t4 + 4][mrow + q + 8];                             \
        }                                                                          \
        _Pragma("unroll")                                                          \
        for (int ni = 0; ni < 8; ni++) {                                           \
            int ncol = n0 + ni * 8 + q;                                            \
            uint32_t bh0 = Bh[BUF][t4][ncol];                                      \
            uint32_t bh1 = Bh[BUF][t4 + 4][ncol];                                  \
            uint32_t bl0 = Bl[BUF][t4][ncol];                                      \
            uint32_t bl1 = Bl[BUF][t4 + 4][ncol];                                  \
            _Pragma("unroll")                                                      \
            for (int mi = 0; mi < 2; mi++) {                                       \
                mma_tf32(acc[mi][ni], ah[mi][0], ah[mi][1], ah[mi][2], ah[mi][3],  \
                         bh0, bh1);                                                \
                mma_tf32(acc[mi][ni], ah[mi][0], ah[mi][1], ah[mi][2], ah[mi][3],  \
                         bl0, bl1);                                                \
                mma_tf32(acc[mi][ni], al[mi][0], al[mi][1], al[mi][2], al[mi][3],  \
                         bh0, bh1);                                                \
            }                                                                      \
        }                                                                          \
    }

    // prologue: tile 0
    {
        float4 va = aok ? *(const float4*)Aptr : make_float4(0.f, 0.f, 0.f, 0.f);
        float4 vb = *(const float4*)Bptr;
        STORE_TILE(0, va, vb)
    }
    __syncthreads();

    int buf = 0;
    for (int k0 = 8; k0 < K; k0 += 8) {
        // issue next-tile global loads BEFORE compute (latency overlap)
        float4 va = aok ? *(const float4*)(Aptr + k0) : make_float4(0.f, 0.f, 0.f, 0.f);
        float4 vb = *(const float4*)(Bptr + (size_t)k0 * Nc);
        COMPUTE_TILE(buf)
        STORE_TILE(buf ^ 1, va, vb)
        __syncthreads();
        buf ^= 1;
    }
    COMPUTE_TILE(buf)

#pragma unroll
    for (int mi = 0; mi < 2; mi++) {
#pragma unroll
        for (int ni = 0; ni < 8; ni++) {
            int col = colBase + n0 + ni * 8 + 2 * t4;
            float bb0 = bias[col], bb1 = bias[col + 1];
            int r0 = rowBase + m0 + mi * 16 + q;
            int r1 = r0 + 8;
            float4 v = acc[mi][ni];
            float o0 = fmaxf(v.x + bb0, 0.f);
            float o1 = fmaxf(v.y + bb1, 0.f);
            float o2 = fmaxf(v.z + bb0, 0.f);
            float o3 = fmaxf(v.w + bb1, 0.f);
            if (r0 < M) *(float2*)(Cm + (size_t)r0 * Nc + col) = make_float2(o0, o1);
            if (r1 < M) *(float2*)(Cm + (size_t)r1 * Nc + col) = make_float2(o2, o3);
        }
    }
}

// ---------------- softmax + argmax: persistent grid-stride -------------------
__global__ void __launch_bounds__(256) k_softmax(const float* __restrict__ logits,
                                                 float* __restrict__ S) {
    int t = threadIdx.x;
    __shared__ float sv[256];
    __shared__ int   si[256];
    for (int i = blockIdx.x; i < NN; i += gridDim.x) {
        const float* row = logits + (size_t)i * CC;
        float v0 = row[t], v1 = row[t + 256];
        float bv = v0; int bi = t;
        if (v1 > bv) { bv = v1; bi = t + 256; }

        sv[t] = bv; si[t] = bi;
        __syncthreads();
        for (int s = 128; s > 0; s >>= 1) {
            if (t < s) {
                float ov = sv[t + s]; int oi = si[t + s];
                if (ov > sv[t] || (ov == sv[t] && oi < si[t])) { sv[t] = ov; si[t] = oi; }
            }
            __syncthreads();
        }
        float m = sv[0];
        if (t == 0) g_cluster[i] = si[0];
        __syncthreads();

        float e0 = expf(v0 - m), e1 = expf(v1 - m);
        sv[t] = e0 + e1;
        __syncthreads();
        for (int s = 128; s > 0; s >>= 1) {
            if (t < s) sv[t] += sv[t + s];
            __syncthreads();
        }
        float invsum = 1.0f / sv[0];
        S[(size_t)i * CC + t]       = e0 * invsum;
        S[(size_t)i * CC + t + 256] = e1 * invsum;
        __syncthreads();
    }
}

// ---------------- fused: hs (x@Ws) + intradeg --------------------------------
__global__ void k_hsintra(const float* __restrict__ x,
                          const float* __restrict__ Ws,
                          const int* __restrict__ ei) {
    int bid = blockIdx.x;
    int t = threadIdx.x;
    if (bid < HSB) {
        int g = bid * 256 + t;
        int w = g >> 5, lane = g & 31;
        if (w >= NN) return;
        float s = 0.f;
        for (int f = lane; f < FF; f += 32) s = fmaf(x[(size_t)w * FF + f], Ws[f], s);
#pragma unroll
        for (int off = 16; off > 0; off >>= 1) s += __shfl_down_sync(0xFFFFFFFF, s, off);
        if (lane == 0) g_hs[w] = s;
    } else {
        int e = (bid - HSB) * 256 + t;
        if (e >= EE) return;
        int s = ei[e], d = ei[EE + e];
        int cs = g_cluster[s], cd = g_cluster[d];
        if (cs == cd) {
            atomicAdd(&g_sdeg[d], 1);
            atomicAdd(&g_icnt[cs], 1);
        }
    }
}

__global__ void k_invs() {
    int i = blockIdx.x * blockDim.x + threadIdx.x;
    if (i < NN) g_invs[i] = rsqrtf((float)g_sdeg[i] + 1.0f);
}

__global__ void k_sagg(const int* __restrict__ ei) {
    int e = blockIdx.x * blockDim.x + threadIdx.x;
    if (e >= EE) return;
    int s = ei[e], d = ei[EE + e];
    if (g_cluster[s] == g_cluster[d])
        atomicAdd(&g_sagg[d], g_invs[s] * g_invs[d] * g_hs[s]);
}

// score + fused segmax
__global__ void k_score(const float* __restrict__ bs) {
    int i = blockIdx.x * blockDim.x + threadIdx.x;
    if (i >= NN) return;
    float inv = g_invs[i];
    float v = g_sagg[i] + inv * inv * g_hs[i] + bs[0];
    float sc = tanhf(v);
    g_score[i] = sc;
    atomicMax(&g_segkey[g_cluster[i]], fkey(sc));
}

__global__ void k_segidx() {
    int i = blockIdx.x * blockDim.x + threadIdx.x;
    if (i >= NN) return;
    int c = g_cluster[i];
    float mx = fdec(g_segkey[c]);
    if (g_score[i] >= mx) atomicMin(&g_segidx[c], i);
}

// ---------------- fused: pool + adjacency ------------------------------------
__global__ void k_pooladj(const float* __restrict__ x,
                          const int* __restrict__ ei,
                          float* __restrict__ out) {
    int bid = blockIdx.x;
    int t = threadIdx.x;
    if (bid < CC) {
        if (t < 128) {
            int c = bid;
            bool ne = g_icnt[c] > 0;
            float alpha = ne ? fdec(g_segkey[c]) : 0.f;
            int idx = min(g_segidx[c], NN - 1);
            out[(size_t)c * FF + t] = x[(size_t)idx * FF + t] * alpha;
        }
    } else {
        int e = (bid - CC) * 256 + t;
        if (e >= EE) return;
        int cs = g_cluster[ei[e]], cd = g_cluster[ei[EE + e]];
        if (cs != cd && g_icnt[cs] > 0 && g_icnt[cd] > 0)
            out[OFF_ADJ + (size_t)cs * CC + cd] = 1.0f;
    }
}

// ---------------- launch ------------------------------------------------------
extern "C" void kernel_launch(void* const* d_in, const int* in_sizes, int n_in,
                              void* d_out, int out_size) {
    const float* x   = (const float*)d_in[0];
    const int*   ei  = (const int*)d_in[1];
    const float* W1  = (const float*)d_in[3];
    const float* b1  = (const float*)d_in[4];
    const float* W2  = (const float*)d_in[5];
    const float* b2  = (const float*)d_in[6];
    const float* W3  = (const float*)d_in[7];
    const float* b3  = (const float*)d_in[8];
    const float* Ws  = (const float*)d_in[9];
    const float* bs  = (const float*)d_in[10];
    float* out = (float*)d_out;

    const int NB = (NN + 255) / 256;
    const int PG128 = 148 * 16;
    const int PG256 = 148 * 8;

    k_initdeg<<<INITB + NB, 256>>>(out, ei);   // 0: init + zero g_deg
    k_scanall<<<1, 1024>>>(ei);                // 1: histogram + scan + inv + cur
    k_fill<<<EB, 256>>>(ei);                   // 2
    k_agg<128><<<PG128, 128>>>(x, g_z);        // 3  [PROFILED: real layer-1 agg]
    {
        dim3 g(HH / 128, (NN + 127) / 128);
        k_tcgemm<<<g, 256>>>(g_z, W1, b1, g_h, NN, FF, HH);
    }
    k_agg<256><<<PG256, 256>>>(g_h, g_z);
    {
        dim3 g(HH / 128, (NN + 127) / 128);
        k_tcgemm<<<g, 256>>>(g_z, W2, b2, g_h, NN, HH, HH);
    }
    k_agg<256><<<PG256, 256>>>(g_h, g_z);
    {
        dim3 g(CC / 128, (NN + 127) / 128);
        k_tcgemm<<<g, 256>>>(g_z, W3, b3, g_h, NN, HH, CC);
    }

    k_softmax<<<PG256, 256>>>(g_h, out + OFF_S);

    k_hsintra<<<HSB + EB, 256>>>(x, Ws, ei);
    k_invs<<<NB, 256>>>();
    k_sagg<<<EB, 256>>>(ei);
    k_score<<<NB, 256>>>(bs);
    k_segidx<<<NB, 256>>>();
    k_pooladj<<<CC + EB, 256>>>(x, ei, out);

    (void)in_sizes; (void)n_in; (void)out_size;
}